// round 8
// baseline (speedup 1.0000x reference)
#include <cuda_runtime.h>
#include <cstdint>

#define BB 2
#define NN 256
#define FF 64
#define HH 64
#define KK 50
#define CC 256

// ---------------- device scratch ----------------
__device__ float g_A [BB*NN*KK];
__device__ float g_Bb[BB*NN*KK];
__device__ float g_U [BB*NN*HH];
__device__ float g_Wp[BB*NN*HH];

typedef unsigned long long ull;

// ---------------- helpers ----------------
__device__ __forceinline__ uint32_t smem_u32(const void* p) {
    uint32_t a;
    asm("{ .reg .u64 t; cvta.to.shared.u64 t, %1; cvt.u32.u64 %0, t; }" : "=r"(a) : "l"(p));
    return a;
}
__device__ __forceinline__ float siluf(float a) { return a * __fdividef(1.f, 1.f + __expf(-a)); }
__device__ __forceinline__ float sigm(float a)  { return __fdividef(1.f, 1.f + __expf(-a)); }
__device__ __forceinline__ float ftanh(float x) {
    float e = __expf(-2.f * fabsf(x));
    return copysignf(__fdividef(1.f - e, 1.f + e), x);
}
__device__ __forceinline__ void fma2(ull& acc, ull a, ull b) {
    asm("fma.rn.f32x2 %0, %1, %2, %0;" : "+l"(acc) : "l"(a), "l"(b));
}
__device__ __forceinline__ ull bcast2(float w) {
    ull r; asm("mov.b64 %0, {%1, %1};" : "=l"(r) : "f"(w)); return r;
}
__device__ __forceinline__ ull pack2(float a, float b) {
    ull r; asm("mov.b64 %0, {%1, %2};" : "=l"(r) : "f"(a), "f"(b)); return r;
}
__device__ __forceinline__ void unpack2(ull v, float& x, float& y) {
    asm("mov.b64 {%0, %1}, %2;" : "=f"(x), "=f"(y) : "l"(v));
}
__device__ __forceinline__ void cp16(uint32_t dst, const void* src) {
    asm volatile("cp.async.cg.shared.global [%0], [%1], 16;" :: "r"(dst), "l"(src) : "memory");
}
#define CP_COMMIT() asm volatile("cp.async.commit_group;" ::: "memory")
#define CP_WAIT0()  asm volatile("cp.async.wait_group 0;" ::: "memory")

// block reduce of 4 floats (8 warps / 256 threads). red >= 36 floats, 16B aligned.
template<int DO_MAX>
__device__ __forceinline__ float4 block_red4(float4 v, int tid, float* red) {
    #pragma unroll
    for (int o = 16; o > 0; o >>= 1) {
        float ax = __shfl_xor_sync(~0u, v.x, o), ay = __shfl_xor_sync(~0u, v.y, o);
        float az = __shfl_xor_sync(~0u, v.z, o), aw = __shfl_xor_sync(~0u, v.w, o);
        if (DO_MAX) { v.x = fmaxf(v.x, ax); v.y = fmaxf(v.y, ay); v.z = fmaxf(v.z, az); v.w = fmaxf(v.w, aw); }
        else        { v.x += ax; v.y += ay; v.z += az; v.w += aw; }
    }
    if ((tid & 31) == 0) ((float4*)red)[tid >> 5] = v;
    __syncthreads();
    if (tid < 32) {
        float4 r;
        if (tid < 8) r = ((float4*)red)[tid];
        else { float id = DO_MAX ? __int_as_float(0xff800000) : 0.f; r = make_float4(id, id, id, id); }
        #pragma unroll
        for (int o = 4; o > 0; o >>= 1) {
            float ax = __shfl_xor_sync(~0u, r.x, o), ay = __shfl_xor_sync(~0u, r.y, o);
            float az = __shfl_xor_sync(~0u, r.z, o), aw = __shfl_xor_sync(~0u, r.w, o);
            if (DO_MAX) { r.x = fmaxf(r.x, ax); r.y = fmaxf(r.y, ay); r.z = fmaxf(r.z, az); r.w = fmaxf(r.w, aw); }
            else        { r.x += ax; r.y += ay; r.z += az; r.w += aw; }
        }
        if (tid == 0) ((float4*)red)[8] = r;
    }
    __syncthreads();
    float4 out = ((float4*)red)[8];
    __syncthreads();
    return out;
}

// ---------------- K0: per-node precompute ----------------
__global__ void prenode_kernel(const float* __restrict__ h,
                               const float* __restrict__ W_in,
                               const float* __restrict__ W_o1) {
    __shared__ float hs[FF];
    int node = blockIdx.x, t = threadIdx.x;
    if (t < FF) hs[t] = h[node * FF + t];
    __syncthreads();
    if (t < KK) {
        float a = 0.f, bv = 0.f;
        #pragma unroll
        for (int f = 0; f < FF; f++) { float hv = hs[f]; a += hv * W_in[f*KK+t]; bv += hv * W_in[(FF+f)*KK+t]; }
        g_A[node*KK+t] = a; g_Bb[node*KK+t] = bv;
    } else if (t >= 64 && t < 128) {
        int c = t - 64;
        float u = 0.f, w = 0.f;
        #pragma unroll
        for (int f = 0; f < FF; f++) { float hv = hs[f]; u += hv * W_o1[f*HH+c]; w += hv * W_o1[(FF+f)*HH+c]; }
        g_U[node*HH+c] = u; g_Wp[node*HH+c] = w;
    }
}

// ---------------- smem layout (float offsets) ----------------
#define O_HE     0        // he[256 j][65] = 16640
#define O_ATT    16640    // 1024
#define O_XDN    17664    // 1024
#define O_CMX    18688    // 256
#define O_CMY    18944
#define O_CMZ    19200
#define O_CN     19456
#define O_P1     19712
#define O_HCOMB  19776
#define O_N1     19840
#define O_HN     19904
#define O_HESUM  19968    // 256
#define O_HI     20224
#define O_WIB    20288
#define O_WON    20352
#define O_BO2    20416
#define O_BI     20480
#define O_MEAN   20544
#define O_BETA   20608
#define O_WS     20672    // 256
#define O_BSG    20928    // 8
#define O_XI     20936    // 4
#define O_RED    20940    // 36 (byte 83760, 16B aligned)
#define O_UNION  21008    // byte 84032, 16B aligned
// phase-1 view of union:
#define O_AS     21008    // 256*51 = 13056
#define O_WO1K   34064    // 50*64 = 3200
#define O_WO2    37264    // 64*64 = 4096 -> 41360
// phase-4 view of union:
#define O_HET    21008    // heTd[256 c][68] = 17408  (32 j duplicated + 16B hole)
#define O_WCH    38416    // 2 * 8192 = 16384 -> 54800
#define SMEM_FLOATS 54800
#define SMEM_BYTES  (SMEM_FLOATS*4)   // 219200

// ---------------- K1: fused per-(b,i) kernel ----------------
__global__ __launch_bounds__(256, 1)
void sake_kernel(const float* __restrict__ h, const float* __restrict__ x,
                 const float* __restrict__ v,
                 const float* __restrict__ means, const float* __restrict__ betas,
                 const float* __restrict__ b_in,
                 const float* __restrict__ W_o1, const float* __restrict__ b_o1,
                 const float* __restrict__ W_o2, const float* __restrict__ b_o2,
                 const float* __restrict__ Ws,  const float* __restrict__ bs,
                 const float* __restrict__ log_gamma,
                 const float* __restrict__ Wx,
                 const float* __restrict__ Wp1, const float* __restrict__ bp1,
                 const float* __restrict__ Wp2, const float* __restrict__ bp2,
                 const float* __restrict__ Wn1, const float* __restrict__ bn1,
                 const float* __restrict__ Wn2, const float* __restrict__ bn2,
                 const float* __restrict__ Wv_mix,
                 const float* __restrict__ Wvel1, const float* __restrict__ bvel1,
                 const float* __restrict__ Wvel2,
                 float* __restrict__ outH, float* __restrict__ outX,
                 float* __restrict__ outV) {
    extern __shared__ float sm[];
    const int tid = threadIdx.x, wid = tid >> 5, lane = tid & 31;
    const int bid = blockIdx.x, b = bid >> 8, i = bid & 255, nodeI = bid;

    float* he    = sm + O_HE;     // [256 j][65]
    float* att_s = sm + O_ATT;    // [256 j][4]
    float* xdn   = sm + O_XDN;    // [256 j][4]
    float* he_e  = sm + O_HESUM;
    float* hi_s  = sm + O_HI;
    float* wib   = sm + O_WIB;
    float* won   = sm + O_WON;
    float* bo2_s = sm + O_BO2;
    float* bi_s  = sm + O_BI;
    float* mn_s  = sm + O_MEAN;
    float* bt_s  = sm + O_BETA;
    float* ws_s  = sm + O_WS;
    float* bsg   = sm + O_BSG;
    float* xi_s  = sm + O_XI;
    float* red   = sm + O_RED;
    float* As    = sm + O_AS;
    float* wo1k  = sm + O_WO1K;
    float* wo2   = sm + O_WO2;
    float* heTd  = sm + O_HET;    // [256 c][68], duplicated j pairs

    const uint32_t smb = smem_u32(sm);

    // ---- preload ----
    if (tid < FF) {
        hi_s[tid]  = h[nodeI*FF+tid];
        wib[tid]   = g_Wp[nodeI*HH+tid] + b_o1[tid];
        won[tid]   = W_o1[178*HH+tid];
        bo2_s[tid] = b_o2[tid];
    }
    if (tid < KK) {
        bi_s[tid] = g_Bb[nodeI*KK+tid] + b_in[tid];
        mn_s[tid] = means[tid];
        bt_s[tid] = betas[tid];
    }
    ws_s[tid] = Ws[tid];
    if (tid < 4) {
        bsg[tid]   = bs[tid];
        bsg[4+tid] = __expf(log_gamma[tid]);
        if (tid < 3) xi_s[tid] = x[nodeI*3+tid];
    }
    for (int idx = tid; idx < NN*KK; idx += 256) {
        int j2 = idx / KK, k = idx - j2*KK;
        As[j2*51+k] = g_A[b*NN*KK + idx];
    }
    for (int idx = tid; idx < NN*HH; idx += 256) {
        int j2 = idx >> 6, f = idx & 63;
        he[j2*65+f] = g_U[b*NN*HH + idx];
    }
    for (int idx = tid; idx < KK*HH; idx += 256) wo1k[idx] = W_o1[128*HH + idx];
    for (int idx = tid; idx < HH*HH; idx += 256) wo2[idx]  = W_o2[idx];
    __syncthreads();

    // ---- phase 1: edge model (thread = j), f32x2 ----
    const int j = tid;
    float xjx = x[(b*NN+j)*3+0], xjy = x[(b*NN+j)*3+1], xjz = x[(b*NN+j)*3+2];
    float dx = xjx - xi_s[0], dy = xjy - xi_s[1], dz = xjz - xi_s[2];
    float d2 = fmaxf(dx*dx + dy*dy + dz*dz, 0.f);
    float normv = sqrtf(d2 + 1e-5f);
    float rinv  = __fdividef(1.f, normv + 1e-5f);
    *(float4*)&xdn[j*4] = make_float4(dx*rinv, dy*rinv, dz*rinv, normv);
    float en = __expf(-normv);

    {
        float accf[64];
        #pragma unroll
        for (int f = 0; f < 64; f++) accf[f] = he[j*65+f] + wib[f] + normv*won[f];
        ull acc2[32];
        #pragma unroll
        for (int f2 = 0; f2 < 32; f2++) acc2[f2] = pack2(accf[2*f2], accf[2*f2+1]);

        #pragma unroll 2
        for (int k = 0; k < KK; k++) {
            float hk = As[j*51+k] + bi_s[k];
            float df = en - mn_s[k];
            float s  = __expf(-bt_s[k]*df*df) * hk;
            ull s2 = bcast2(s);
            const ulonglong2* wr = (const ulonglong2*)&wo1k[k*64];
            #pragma unroll
            for (int f4 = 0; f4 < 16; f4++) {
                ulonglong2 wv = wr[f4];
                fma2(acc2[2*f4],   wv.x, s2);
                fma2(acc2[2*f4+1], wv.y, s2);
            }
        }
        #pragma unroll
        for (int f2 = 0; f2 < 32; f2++) {
            float a0, a1; unpack2(acc2[f2], a0, a1);
            accf[2*f2] = siluf(a0); accf[2*f2+1] = siluf(a1);
        }

        #pragma unroll
        for (int g = 0; g < 4; g++) {
            ull o2[8];
            const ulonglong2* bo = (const ulonglong2*)&bo2_s[g*16];
            #pragma unroll
            for (int q = 0; q < 4; q++) { ulonglong2 bv = bo[q]; o2[2*q] = bv.x; o2[2*q+1] = bv.y; }
            #pragma unroll 8
            for (int f = 0; f < 64; f++) {
                ull ab = bcast2(accf[f]);
                const ulonglong2* wr = (const ulonglong2*)&wo2[f*64 + g*16];
                #pragma unroll
                for (int q = 0; q < 4; q++) {
                    ulonglong2 wv = wr[q];
                    fma2(o2[2*q],   wv.x, ab);
                    fma2(o2[2*q+1], wv.y, ab);
                }
            }
            #pragma unroll
            for (int q = 0; q < 8; q++) {
                float r0, r1; unpack2(o2[q], r0, r1);
                he[j*65 + g*16 + 2*q]     = r0;
                he[j*65 + g*16 + 2*q + 1] = r1;
            }
        }
    }

    // ---- phase 2: attentions (softmax over j) ----
    float z0 = bsg[0], z1 = bsg[1], z2 = bsg[2], z3 = bsg[3];
    for (int f = 0; f < 64; f++) {
        float a = he[j*65+f];
        z0 += a*ws_s[f*4+0]; z1 += a*ws_s[f*4+1]; z2 += a*ws_s[f*4+2]; z3 += a*ws_s[f*4+3];
    }
    z0 = (z0 > 0.f) ? z0 : 2.f*(__expf(0.5f*z0) - 1.f);
    z1 = (z1 > 0.f) ? z1 : 2.f*(__expf(0.5f*z1) - 1.f);
    z2 = (z2 > 0.f) ? z2 : 2.f*(__expf(0.5f*z2) - 1.f);
    z3 = (z3 > 0.f) ? z3 : 2.f*(__expf(0.5f*z3) - 1.f);
    float diag = (j == i) ? 1e5f : 0.f;
    float4 el = make_float4(-(normv+diag)*bsg[4], -(normv+diag)*bsg[5],
                            -(normv+diag)*bsg[6], -(normv+diag)*bsg[7]);
    float4 sl = make_float4(z0-diag, z1-diag, z2-diag, z3-diag);

    float4 m  = block_red4<1>(el, tid, red);
    float4 ee = make_float4(__expf(el.x-m.x), __expf(el.y-m.y), __expf(el.z-m.z), __expf(el.w-m.w));
    float4 s  = block_red4<0>(ee, tid, red);
    float4 eucl = make_float4(__fdividef(ee.x,s.x), __fdividef(ee.y,s.y),
                              __fdividef(ee.z,s.z), __fdividef(ee.w,s.w));
    m  = block_red4<1>(sl, tid, red);
    ee = make_float4(__expf(sl.x-m.x), __expf(sl.y-m.y), __expf(sl.z-m.z), __expf(sl.w-m.w));
    s  = block_red4<0>(ee, tid, red);
    float4 sem = make_float4(__fdividef(ee.x,s.x), __fdividef(ee.y,s.y),
                             __fdividef(ee.z,s.z), __fdividef(ee.w,s.w));
    float4 q4 = make_float4(eucl.x*sem.x, eucl.y*sem.y, eucl.z*sem.z, eucl.w*sem.w);
    m  = block_red4<1>(q4, tid, red);
    ee = make_float4(__expf(q4.x-m.x), __expf(q4.y-m.y), __expf(q4.z-m.z), __expf(q4.w-m.w));
    s  = block_red4<0>(ee, tid, red);
    att_s[j*4+0] = __fdividef(ee.x, s.x);
    att_s[j*4+1] = __fdividef(ee.y, s.y);
    att_s[j*4+2] = __fdividef(ee.z, s.z);
    att_s[j*4+3] = __fdividef(ee.w, s.w);
    __syncthreads();

    // ---- phase 3: h_e = sum_j he_att ----
    {
        const int fcol = tid >> 2, hd = tid & 3;
        float hs = 0.f;
        for (int jj = 0; jj < NN; jj++) hs += he[jj*65+fcol] * att_s[jj*4+hd];
        he_e[tid] = hs;
    }
    __syncthreads();   // phase-1 union dead -> heTd / Wx ring

    // ---- phase 4: coeff = tanh(he_att @ Wx), reduced over j ----
    // 8 warps = 8 n-slices of 32 n. lane = jp(0..7)*4 + nq(0..3).
    // Thread tile: 4 j (duplicated-pair loads, broadcast) x 8 n (packed pairs).
    // Pass = 32 j; 8 passes; ring of 2 x 32c Wx chunks.
    {
        const int jp = lane >> 2, nq = lane & 3;
        const int nb = wid*32 + nq*8;
        const int aoff = jp*8 + ((jp >= 4) ? 4 : 0);    // 16B hole after 128B
        const int fme = tid >> 2, hme = tid & 3;
        const int rot = ((lane >> 3) & 3) * 4;          // STS bank-conflict fix
        float cmx[8] = {0,0,0,0,0,0,0,0};
        float cmy[8] = {0,0,0,0,0,0,0,0};
        float cmz[8] = {0,0,0,0,0,0,0,0};

        #define STAGE(chunk, buf) do { \
            uint32_t _dst = smb + (uint32_t)(O_WCH + (buf)*8192)*4u + (uint32_t)tid*16u; \
            const float* _src = Wx + (chunk)*8192 + tid*4; \
            _Pragma("unroll") \
            for (int _r = 0; _r < 8; _r++) cp16(_dst + _r*4096u, _src + _r*1024); \
            CP_COMMIT(); \
        } while(0)

        for (int pass = 0; pass < 8; pass++) {
            const int j0 = pass*32;
            __syncthreads();            // prev pass ring + heTd fully consumed
            STAGE(0, 0);
            // fill heTd[c][jj] = dup(he[j0+jj][fme] * att[j0+jj][hme]), c = tid
            #pragma unroll 8
            for (int u = 0; u < 32; u++) {
                int jjl = (u + rot) & 31;
                int jn = j0 + jjl;
                float val = he[jn*65 + fme] * att_s[jn*4 + hme];
                int off = jjl*2 + ((jjl & 16) ? 4 : 0);
                *(ull*)&heTd[tid*68 + off] = bcast2(val);
            }

            ull acc[4][4];
            #pragma unroll
            for (int q = 0; q < 4; q++)
                #pragma unroll
                for (int p = 0; p < 4; p++) acc[q][p] = 0ull;

            for (int t = 0; t < 8; t++) {
                CP_WAIT0();
                __syncthreads();        // buf t&1 + heTd visible; compute(t-1) done
                if (t < 7) STAGE(t+1, (t+1)&1);

                const float* wb = sm + O_WCH + (t&1)*8192;
                const float* arow = heTd + t*32*68 + aoff;
                #pragma unroll 8
                for (int cc = 0; cc < 32; cc++) {
                    ulonglong2 aA = *(const ulonglong2*)(arow + cc*68);        // (a0,a0),(a1,a1)
                    ulonglong2 aB = *(const ulonglong2*)(arow + cc*68 + 4);    // (a2,a2),(a3,a3)
                    ulonglong2 wA = *(const ulonglong2*)(wb + cc*256 + nb);    // n0..3
                    ulonglong2 wB = *(const ulonglong2*)(wb + cc*256 + nb + 4);// n4..7
                    fma2(acc[0][0], wA.x, aA.x); fma2(acc[0][1], wA.y, aA.x);
                    fma2(acc[0][2], wB.x, aA.x); fma2(acc[0][3], wB.y, aA.x);
                    fma2(acc[1][0], wA.x, aA.y); fma2(acc[1][1], wA.y, aA.y);
                    fma2(acc[1][2], wB.x, aA.y); fma2(acc[1][3], wB.y, aA.y);
                    fma2(acc[2][0], wA.x, aB.x); fma2(acc[2][1], wA.y, aB.x);
                    fma2(acc[2][2], wB.x, aB.x); fma2(acc[2][3], wB.y, aB.x);
                    fma2(acc[3][0], wA.x, aB.y); fma2(acc[3][1], wA.y, aB.y);
                    fma2(acc[3][2], wB.x, aB.y); fma2(acc[3][3], wB.y, aB.y);
                }
            }

            // epilogue: tanh + xd-weighted accumulate (per-n registers)
            #pragma unroll
            for (int q = 0; q < 4; q++) {
                float4 xd4 = *(const float4*)&xdn[(j0 + jp*4 + q)*4];
                #pragma unroll
                for (int p = 0; p < 4; p++) {
                    float c0, c1; unpack2(acc[q][p], c0, c1);
                    float t0 = ftanh(c0), t1 = ftanh(c1);
                    cmx[2*p]   += xd4.x*t0; cmy[2*p]   += xd4.y*t0; cmz[2*p]   += xd4.z*t0;
                    cmx[2*p+1] += xd4.x*t1; cmy[2*p+1] += xd4.y*t1; cmz[2*p+1] += xd4.z*t1;
                }
            }
        }

        // reduce over jp groups (lane bits 2,3,4); lanes jp==0 store n-exclusive
        #pragma unroll
        for (int n = 0; n < 8; n++) {
            #pragma unroll
            for (int o = 4; o <= 16; o <<= 1) {
                cmx[n] += __shfl_xor_sync(~0u, cmx[n], o);
                cmy[n] += __shfl_xor_sync(~0u, cmy[n], o);
                cmz[n] += __shfl_xor_sync(~0u, cmz[n], o);
            }
        }
        if (jp == 0) {
            #pragma unroll
            for (int n = 0; n < 8; n++) {
                sm[O_CMX + nb + n] = cmx[n];
                sm[O_CMY + nb + n] = cmy[n];
                sm[O_CMZ + nb + n] = cmz[n];
            }
        }
    }
    __syncthreads();

    // ---- phase 5: comb_sum / comb_norm / delta_v ----
    float* cn    = sm + O_CN;
    float* p1_s  = sm + O_P1;
    float* hcomb = sm + O_HCOMB;
    float* n1_s  = sm + O_N1;
    float* hn_s  = sm + O_HN;
    const float invN = 1.f/256.f;
    float csx = sm[O_CMX + tid]*invN, csy = sm[O_CMY + tid]*invN, csz = sm[O_CMZ + tid]*invN;
    cn[tid] = csx*csx + csy*csy + csz*csz;
    float wv = Wv_mix[tid];
    float4 dv4 = block_red4<0>(make_float4(wv*csx, wv*csy, wv*csz, 0.f), tid, red);

    // ---- phase 6: tail MLPs ----
    if (tid < 64) {
        float a = bp1[tid];
        for (int c = 0; c < CC; c++) a += cn[c] * Wp1[c*64+tid];
        p1_s[tid] = siluf(a);
    }
    __syncthreads();
    if (tid < 64) {
        float a = bp2[tid];
        for (int f = 0; f < 64; f++) a += p1_s[f] * Wp2[f*64+tid];
        hcomb[tid] = siluf(a);
    }
    __syncthreads();
    if (tid < 64) {
        float a = bn1[tid];
        for (int f = 0; f < 64; f++) a += hi_s[f]  * Wn1[f*64+tid];
        for (int c = 0; c < CC; c++) a += he_e[c]  * Wn1[(64+c)*64+tid];
        for (int f = 0; f < 64; f++) a += hcomb[f] * Wn1[(320+f)*64+tid];
        n1_s[tid] = siluf(a);
    }
    __syncthreads();
    if (tid < 64) {
        float a = bn2[tid];
        for (int f = 0; f < 64; f++) a += n1_s[f] * Wn2[f*64+tid];
        float hv = hi_s[tid] + siluf(a);
        hn_s[tid] = hv;
        outH[nodeI*64+tid] = hv;
    }
    __syncthreads();
    float vl = 0.f;
    if (tid < 64) {
        float a = bvel1[tid];
        for (int f = 0; f < 64; f++) a += hn_s[f] * Wvel1[f*64+tid];
        vl = siluf(a) * Wvel2[tid];
    }
    float4 vs = block_red4<0>(make_float4(vl, 0.f, 0.f, 0.f), tid, red);
    if (tid == 0) {
        float scale = 2.f * sigm(vs.x);
        float dvv[3] = {dv4.x, dv4.y, dv4.z};
        #pragma unroll
        for (int t = 0; t < 3; t++) {
            float vn = dvv[t] + scale * v[nodeI*3+t];
            outV[nodeI*3+t] = vn;
            outX[nodeI*3+t] = x[nodeI*3+t] + vn;
        }
    }
}

// ---------------- launch ----------------
extern "C" void kernel_launch(void* const* d_in, const int* in_sizes, int n_in,
                              void* d_out, int out_size) {
    const float* h      = (const float*)d_in[0];
    const float* x      = (const float*)d_in[1];
    const float* v      = (const float*)d_in[2];
    const float* means  = (const float*)d_in[3];
    const float* betas  = (const float*)d_in[4];
    const float* W_in   = (const float*)d_in[5];
    const float* b_in   = (const float*)d_in[6];
    const float* W_o1   = (const float*)d_in[7];
    const float* b_o1   = (const float*)d_in[8];
    const float* W_o2   = (const float*)d_in[9];
    const float* b_o2   = (const float*)d_in[10];
    const float* Ws     = (const float*)d_in[11];
    const float* bs     = (const float*)d_in[12];
    const float* lgam   = (const float*)d_in[13];
    const float* Wx     = (const float*)d_in[14];
    const float* Wp1    = (const float*)d_in[15];
    const float* bp1    = (const float*)d_in[16];
    const float* Wp2    = (const float*)d_in[17];
    const float* bp2    = (const float*)d_in[18];
    const float* Wn1    = (const float*)d_in[19];
    const float* bn1    = (const float*)d_in[20];
    const float* Wn2    = (const float*)d_in[21];
    const float* bn2    = (const float*)d_in[22];
    const float* Wv_mix = (const float*)d_in[23];
    const float* Wvel1  = (const float*)d_in[24];
    const float* bvel1  = (const float*)d_in[25];
    const float* Wvel2  = (const float*)d_in[26];

    float* out  = (float*)d_out;
    float* outH = out;
    float* outX = out + BB*NN*FF;
    float* outV = outX + BB*NN*3;

    cudaFuncSetAttribute(sake_kernel, cudaFuncAttributeMaxDynamicSharedMemorySize, SMEM_BYTES);

    prenode_kernel<<<BB*NN, 128>>>(h, W_in, W_o1);
    sake_kernel<<<BB*NN, 256, SMEM_BYTES>>>(
        h, x, v, means, betas, b_in, W_o1, b_o1, W_o2, b_o2,
        Ws, bs, lgam, Wx, Wp1, bp1, Wp2, bp2,
        Wn1, bn1, Wn2, bn2, Wv_mix, Wvel1, bvel1, Wvel2,
        outH, outX, outV);
}

// round 9
// speedup vs baseline: 1.3621x; 1.3621x over previous
#include <cuda_runtime.h>
#include <cstdint>

#define BB 2
#define NN 256
#define FF 64
#define HH 64
#define KK 50
#define CC 256

// ---------------- device scratch ----------------
__device__ float g_A [BB*NN*KK];
__device__ float g_Bb[BB*NN*KK];
__device__ float g_U [BB*NN*HH];
__device__ float g_Wp[BB*NN*HH];

typedef unsigned long long ull;

// ---------------- helpers ----------------
__device__ __forceinline__ uint32_t smem_u32(const void* p) {
    uint32_t a;
    asm("{ .reg .u64 t; cvta.to.shared.u64 t, %1; cvt.u32.u64 %0, t; }" : "=r"(a) : "l"(p));
    return a;
}
__device__ __forceinline__ float siluf(float a) { return a * __fdividef(1.f, 1.f + __expf(-a)); }
__device__ __forceinline__ float sigm(float a)  { return __fdividef(1.f, 1.f + __expf(-a)); }
__device__ __forceinline__ float ftanh(float x) {
    float e = __expf(-2.f * fabsf(x));
    return copysignf(__fdividef(1.f - e, 1.f + e), x);
}
__device__ __forceinline__ void fma2(ull& acc, ull a, ull b) {
    asm("fma.rn.f32x2 %0, %1, %2, %0;" : "+l"(acc) : "l"(a), "l"(b));
}
__device__ __forceinline__ ull bcast2(float w) {
    ull r; asm("mov.b64 %0, {%1, %1};" : "=l"(r) : "f"(w)); return r;
}
__device__ __forceinline__ ull pack2(float a, float b) {
    ull r; asm("mov.b64 %0, {%1, %2};" : "=l"(r) : "f"(a), "f"(b)); return r;
}
__device__ __forceinline__ void unpack2(ull v, float& x, float& y) {
    asm("mov.b64 {%0, %1}, %2;" : "=f"(x), "=f"(y) : "l"(v));
}
__device__ __forceinline__ void cp16(uint32_t dst, const void* src) {
    asm volatile("cp.async.cg.shared.global [%0], [%1], 16;" :: "r"(dst), "l"(src) : "memory");
}
#define CP_COMMIT() asm volatile("cp.async.commit_group;" ::: "memory")
#define CP_WAIT0()  asm volatile("cp.async.wait_group 0;" ::: "memory")

// block reduce of 4 floats (8 warps / 256 threads). red >= 36 floats, 16B aligned.
template<int DO_MAX>
__device__ __forceinline__ float4 block_red4(float4 v, int tid, float* red) {
    #pragma unroll
    for (int o = 16; o > 0; o >>= 1) {
        float ax = __shfl_xor_sync(~0u, v.x, o), ay = __shfl_xor_sync(~0u, v.y, o);
        float az = __shfl_xor_sync(~0u, v.z, o), aw = __shfl_xor_sync(~0u, v.w, o);
        if (DO_MAX) { v.x = fmaxf(v.x, ax); v.y = fmaxf(v.y, ay); v.z = fmaxf(v.z, az); v.w = fmaxf(v.w, aw); }
        else        { v.x += ax; v.y += ay; v.z += az; v.w += aw; }
    }
    if ((tid & 31) == 0) ((float4*)red)[tid >> 5] = v;
    __syncthreads();
    if (tid < 32) {
        float4 r;
        if (tid < 8) r = ((float4*)red)[tid];
        else { float id = DO_MAX ? __int_as_float(0xff800000) : 0.f; r = make_float4(id, id, id, id); }
        #pragma unroll
        for (int o = 4; o > 0; o >>= 1) {
            float ax = __shfl_xor_sync(~0u, r.x, o), ay = __shfl_xor_sync(~0u, r.y, o);
            float az = __shfl_xor_sync(~0u, r.z, o), aw = __shfl_xor_sync(~0u, r.w, o);
            if (DO_MAX) { r.x = fmaxf(r.x, ax); r.y = fmaxf(r.y, ay); r.z = fmaxf(r.z, az); r.w = fmaxf(r.w, aw); }
            else        { r.x += ax; r.y += ay; r.z += az; r.w += aw; }
        }
        if (tid == 0) ((float4*)red)[8] = r;
    }
    __syncthreads();
    float4 out = ((float4*)red)[8];
    __syncthreads();
    return out;
}

// ---------------- K0: per-node precompute ----------------
__global__ void prenode_kernel(const float* __restrict__ h,
                               const float* __restrict__ W_in,
                               const float* __restrict__ W_o1) {
    __shared__ float hs[FF];
    int node = blockIdx.x, t = threadIdx.x;
    if (t < FF) hs[t] = h[node * FF + t];
    __syncthreads();
    if (t < KK) {
        float a = 0.f, bv = 0.f;
        #pragma unroll
        for (int f = 0; f < FF; f++) { float hv = hs[f]; a += hv * W_in[f*KK+t]; bv += hv * W_in[(FF+f)*KK+t]; }
        g_A[node*KK+t] = a; g_Bb[node*KK+t] = bv;
    } else if (t >= 64 && t < 128) {
        int c = t - 64;
        float u = 0.f, w = 0.f;
        #pragma unroll
        for (int f = 0; f < FF; f++) { float hv = hs[f]; u += hv * W_o1[f*HH+c]; w += hv * W_o1[(FF+f)*HH+c]; }
        g_U[node*HH+c] = u; g_Wp[node*HH+c] = w;
    }
}

// ---------------- smem layout (float offsets) ----------------
#define O_HE     0        // 256*65 = 16640
#define O_ATT    16640    // 1024
#define O_XDN    17664    // 1024
#define O_CMX    18688    // 256 (also phase-6 partial scratch)
#define O_CMY    18944
#define O_CMZ    19200
#define O_CN     19456
#define O_P1     19712
#define O_HCOMB  19776
#define O_N1     19840
#define O_HN     19904
#define O_HESUM  23808    // 256
#define O_HI     24064
#define O_WIB    24128
#define O_WON    24192
#define O_BO2    24256
#define O_BI     24320
#define O_MEAN   24384
#define O_BETA   24448
#define O_WS     24512    // 256
#define O_BSG    24768    // 8
#define O_XI     24776    // 4
#define O_RED    24784    // 36
#define O_UNION  24832
// phase-1 view of union:
#define O_AS     24832    // 256*51 = 13056
#define O_WO1K   37888    // 3200
#define O_WO2    41088    // 4096 -> 45184
// phase-4 view of union:
#define O_HET    24832    // heT[256 c][76] = 19456 (4 groups of 16 j + 4-float holes)
#define O_WCH    44288    // 2 * 4096 = 8192 -> 52480
// phase-6 view: cat[384] at O_HET (heT dead)
#define SMEM_FLOATS 52480
#define SMEM_BYTES  (SMEM_FLOATS*4)   // 209920

// ---------------- K1: fused per-(b,i) kernel ----------------
__global__ __launch_bounds__(256, 1)
void sake_kernel(const float* __restrict__ h, const float* __restrict__ x,
                 const float* __restrict__ v,
                 const float* __restrict__ means, const float* __restrict__ betas,
                 const float* __restrict__ b_in,
                 const float* __restrict__ W_o1, const float* __restrict__ b_o1,
                 const float* __restrict__ W_o2, const float* __restrict__ b_o2,
                 const float* __restrict__ Ws,  const float* __restrict__ bs,
                 const float* __restrict__ log_gamma,
                 const float* __restrict__ Wx,
                 const float* __restrict__ Wp1, const float* __restrict__ bp1,
                 const float* __restrict__ Wp2, const float* __restrict__ bp2,
                 const float* __restrict__ Wn1, const float* __restrict__ bn1,
                 const float* __restrict__ Wn2, const float* __restrict__ bn2,
                 const float* __restrict__ Wv_mix,
                 const float* __restrict__ Wvel1, const float* __restrict__ bvel1,
                 const float* __restrict__ Wvel2,
                 float* __restrict__ outH, float* __restrict__ outX,
                 float* __restrict__ outV) {
    extern __shared__ float sm[];
    const int tid = threadIdx.x, wid = tid >> 5, lane = tid & 31;
    const int bid = blockIdx.x, b = bid >> 8, i = bid & 255, nodeI = bid;

    float* he    = sm + O_HE;     // [256 j][65]
    float* att_s = sm + O_ATT;    // [256 j][4]
    float* xdn   = sm + O_XDN;    // [256 j][4]
    float* he_e  = sm + O_HESUM;
    float* hi_s  = sm + O_HI;
    float* wib   = sm + O_WIB;
    float* won   = sm + O_WON;
    float* bo2_s = sm + O_BO2;
    float* bi_s  = sm + O_BI;
    float* mn_s  = sm + O_MEAN;
    float* bt_s  = sm + O_BETA;
    float* ws_s  = sm + O_WS;
    float* bsg   = sm + O_BSG;
    float* xi_s  = sm + O_XI;
    float* red   = sm + O_RED;
    float* As    = sm + O_AS;
    float* wo1k  = sm + O_WO1K;
    float* wo2   = sm + O_WO2;
    float* heT   = sm + O_HET;    // [256 c][76]

    const uint32_t smb = smem_u32(sm);

    // ---- preload ----
    if (tid < FF) {
        hi_s[tid]  = h[nodeI*FF+tid];
        wib[tid]   = g_Wp[nodeI*HH+tid] + b_o1[tid];
        won[tid]   = W_o1[178*HH+tid];
        bo2_s[tid] = b_o2[tid];
    }
    if (tid < KK) {
        bi_s[tid] = g_Bb[nodeI*KK+tid] + b_in[tid];
        mn_s[tid] = means[tid];
        bt_s[tid] = betas[tid];
    }
    ws_s[tid] = Ws[tid];
    if (tid < 4) {
        bsg[tid]   = bs[tid];
        bsg[4+tid] = __expf(log_gamma[tid]);
        if (tid < 3) xi_s[tid] = x[nodeI*3+tid];
    }
    for (int idx = tid; idx < NN*KK; idx += 256) {
        int j2 = idx / KK, k = idx - j2*KK;
        As[j2*51+k] = g_A[b*NN*KK + idx];
    }
    for (int idx = tid; idx < NN*HH; idx += 256) {
        int j2 = idx >> 6, f = idx & 63;
        he[j2*65+f] = g_U[b*NN*HH + idx];
    }
    for (int idx = tid; idx < KK*HH; idx += 256) wo1k[idx] = W_o1[128*HH + idx];
    for (int idx = tid; idx < HH*HH; idx += 256) wo2[idx]  = W_o2[idx];
    __syncthreads();

    // ---- phase 1: edge model (thread = j), f32x2 ----
    const int j = tid;
    float xjx = x[(b*NN+j)*3+0], xjy = x[(b*NN+j)*3+1], xjz = x[(b*NN+j)*3+2];
    float dx = xjx - xi_s[0], dy = xjy - xi_s[1], dz = xjz - xi_s[2];
    float d2 = fmaxf(dx*dx + dy*dy + dz*dz, 0.f);
    float normv = sqrtf(d2 + 1e-5f);
    float rinv  = __fdividef(1.f, normv + 1e-5f);
    *(float4*)&xdn[j*4] = make_float4(dx*rinv, dy*rinv, dz*rinv, normv);
    float en = __expf(-normv);

    {
        float accf[64];
        #pragma unroll
        for (int f = 0; f < 64; f++) accf[f] = he[j*65+f] + wib[f] + normv*won[f];
        ull acc2[32];
        #pragma unroll
        for (int f2 = 0; f2 < 32; f2++) acc2[f2] = pack2(accf[2*f2], accf[2*f2+1]);

        #pragma unroll 2
        for (int k = 0; k < KK; k++) {
            float hk = As[j*51+k] + bi_s[k];
            float df = en - mn_s[k];
            float s  = __expf(-bt_s[k]*df*df) * hk;
            ull s2 = bcast2(s);
            const ulonglong2* wr = (const ulonglong2*)&wo1k[k*64];
            #pragma unroll
            for (int f4 = 0; f4 < 16; f4++) {
                ulonglong2 wv = wr[f4];
                fma2(acc2[2*f4],   wv.x, s2);
                fma2(acc2[2*f4+1], wv.y, s2);
            }
        }
        #pragma unroll
        for (int f2 = 0; f2 < 32; f2++) {
            float a0, a1; unpack2(acc2[f2], a0, a1);
            accf[2*f2] = siluf(a0); accf[2*f2+1] = siluf(a1);
        }

        #pragma unroll
        for (int g = 0; g < 4; g++) {
            ull o2[8];
            const ulonglong2* bo = (const ulonglong2*)&bo2_s[g*16];
            #pragma unroll
            for (int q = 0; q < 4; q++) { ulonglong2 bv = bo[q]; o2[2*q] = bv.x; o2[2*q+1] = bv.y; }
            #pragma unroll 8
            for (int f = 0; f < 64; f++) {
                ull ab = bcast2(accf[f]);
                const ulonglong2* wr = (const ulonglong2*)&wo2[f*64 + g*16];
                #pragma unroll
                for (int q = 0; q < 4; q++) {
                    ulonglong2 wv = wr[q];
                    fma2(o2[2*q],   wv.x, ab);
                    fma2(o2[2*q+1], wv.y, ab);
                }
            }
            #pragma unroll
            for (int q = 0; q < 8; q++) {
                float r0, r1; unpack2(o2[q], r0, r1);
                he[j*65 + g*16 + 2*q]     = r0;
                he[j*65 + g*16 + 2*q + 1] = r1;
            }
        }
    }

    // ---- phase 2: attentions (softmax over j) ----
    float z0 = bsg[0], z1 = bsg[1], z2 = bsg[2], z3 = bsg[3];
    for (int f = 0; f < 64; f++) {
        float a = he[j*65+f];
        z0 += a*ws_s[f*4+0]; z1 += a*ws_s[f*4+1]; z2 += a*ws_s[f*4+2]; z3 += a*ws_s[f*4+3];
    }
    z0 = (z0 > 0.f) ? z0 : 2.f*(__expf(0.5f*z0) - 1.f);
    z1 = (z1 > 0.f) ? z1 : 2.f*(__expf(0.5f*z1) - 1.f);
    z2 = (z2 > 0.f) ? z2 : 2.f*(__expf(0.5f*z2) - 1.f);
    z3 = (z3 > 0.f) ? z3 : 2.f*(__expf(0.5f*z3) - 1.f);
    float diag = (j == i) ? 1e5f : 0.f;
    float4 el = make_float4(-(normv+diag)*bsg[4], -(normv+diag)*bsg[5],
                            -(normv+diag)*bsg[6], -(normv+diag)*bsg[7]);
    float4 sl = make_float4(z0-diag, z1-diag, z2-diag, z3-diag);

    float4 m  = block_red4<1>(el, tid, red);
    float4 ee = make_float4(__expf(el.x-m.x), __expf(el.y-m.y), __expf(el.z-m.z), __expf(el.w-m.w));
    float4 s  = block_red4<0>(ee, tid, red);
    float4 eucl = make_float4(__fdividef(ee.x,s.x), __fdividef(ee.y,s.y),
                              __fdividef(ee.z,s.z), __fdividef(ee.w,s.w));
    m  = block_red4<1>(sl, tid, red);
    ee = make_float4(__expf(sl.x-m.x), __expf(sl.y-m.y), __expf(sl.z-m.z), __expf(sl.w-m.w));
    s  = block_red4<0>(ee, tid, red);
    float4 sem = make_float4(__fdividef(ee.x,s.x), __fdividef(ee.y,s.y),
                             __fdividef(ee.z,s.z), __fdividef(ee.w,s.w));
    float4 q4 = make_float4(eucl.x*sem.x, eucl.y*sem.y, eucl.z*sem.z, eucl.w*sem.w);
    m  = block_red4<1>(q4, tid, red);
    ee = make_float4(__expf(q4.x-m.x), __expf(q4.y-m.y), __expf(q4.z-m.z), __expf(q4.w-m.w));
    s  = block_red4<0>(ee, tid, red);
    att_s[j*4+0] = __fdividef(ee.x, s.x);
    att_s[j*4+1] = __fdividef(ee.y, s.y);
    att_s[j*4+2] = __fdividef(ee.z, s.z);
    att_s[j*4+3] = __fdividef(ee.w, s.w);
    __syncthreads();   // phase-1 union dead after phase 4's first fill uses he/att only

    // ---- phase 4: coeff = tanh(he_att @ Wx), reduced over j ----
    // 8 warps = 8 n-slices of 32 n. lane = jp(0..3)*8 + nq(0..7).
    // Thread tile: 16 j (8 packed pairs) x 4 n. Pass = 64 j; 4 passes.
    // heT[c][76]: group g of 16 j at float offset g*20 (4-float holes -> banks 0/20/8/28).
    // (phase 3 folded in: he_e accumulated during fill)
    {
        const int jp = lane >> 3, nq = lane & 7;
        const int nb = wid*32 + nq*4;
        const int fme = tid >> 2, hme = tid & 3;
        float cmx[4] = {0,0,0,0}, cmy[4] = {0,0,0,0}, cmz[4] = {0,0,0,0};
        float heE = 0.f;

        #define STAGE(chunk, buf) do { \
            uint32_t _dst = smb + (uint32_t)(O_WCH + (buf)*4096)*4u + (uint32_t)tid*16u; \
            const float* _src = Wx + (chunk)*4096 + tid*4; \
            cp16(_dst,          _src); \
            cp16(_dst + 4096u,  _src + 1024); \
            cp16(_dst + 8192u,  _src + 2048); \
            cp16(_dst + 12288u, _src + 3072); \
            CP_COMMIT(); \
        } while(0)

        for (int pass = 0; pass < 4; pass++) {
            const int j0 = pass*64;
            __syncthreads();            // prev pass ring + heT fully consumed
            STAGE(0, 0);
            // fill heT[c=tid][64 j of this pass] + accumulate he_e
            #pragma unroll 8
            for (int jj = 0; jj < 64; jj += 2) {
                int jn = j0 + jj;
                float v0 = he[jn*65 + fme]     * att_s[jn*4 + hme];
                float v1 = he[(jn+1)*65 + fme] * att_s[(jn+1)*4 + hme];
                heE += v0 + v1;
                int off = ((jj >> 4)*20) + (jj & 15);
                *(ull*)&heT[tid*76 + off] = pack2(v0, v1);
            }

            ull acc[4][8];
            #pragma unroll
            for (int n = 0; n < 4; n++)
                #pragma unroll
                for (int p = 0; p < 8; p++) acc[n][p] = 0ull;

            for (int t = 0; t < 16; t++) {
                CP_WAIT0();
                __syncthreads();        // buf t&1 + heT visible; compute(t-1) done
                if (t < 15) STAGE(t+1, (t+1)&1);

                const float* wb = sm + O_WCH + (t&1)*4096;
                const int cb = t*16;
                #pragma unroll 4
                for (int cc = 0; cc < 16; cc++) {
                    const float* ar = heT + (cb+cc)*76 + jp*20;
                    ulonglong2 a0 = *(const ulonglong2*)(ar);
                    ulonglong2 a1 = *(const ulonglong2*)(ar + 4);
                    ulonglong2 a2 = *(const ulonglong2*)(ar + 8);
                    ulonglong2 a3 = *(const ulonglong2*)(ar + 12);
                    float4 w4 = *(const float4*)&wb[cc*256 + nb];
                    ull bb[4];
                    bb[0] = bcast2(w4.x); bb[1] = bcast2(w4.y);
                    bb[2] = bcast2(w4.z); bb[3] = bcast2(w4.w);
                    #pragma unroll
                    for (int n = 0; n < 4; n++) {
                        fma2(acc[n][0], a0.x, bb[n]); fma2(acc[n][1], a0.y, bb[n]);
                        fma2(acc[n][2], a1.x, bb[n]); fma2(acc[n][3], a1.y, bb[n]);
                        fma2(acc[n][4], a2.x, bb[n]); fma2(acc[n][5], a2.y, bb[n]);
                        fma2(acc[n][6], a3.x, bb[n]); fma2(acc[n][7], a3.y, bb[n]);
                    }
                }
            }

            // epilogue: tanh + xd-weighted accumulate
            #pragma unroll
            for (int p = 0; p < 8; p++) {
                float4 x0 = *(const float4*)&xdn[(j0 + jp*16 + 2*p)*4];
                float4 x1 = *(const float4*)&xdn[(j0 + jp*16 + 2*p + 1)*4];
                #pragma unroll
                for (int n = 0; n < 4; n++) {
                    float c0, c1; unpack2(acc[n][p], c0, c1);
                    float t0 = ftanh(c0), t1 = ftanh(c1);
                    cmx[n] += x0.x*t0 + x1.x*t1;
                    cmy[n] += x0.y*t0 + x1.y*t1;
                    cmz[n] += x0.z*t0 + x1.z*t1;
                }
            }
        }
        he_e[tid] = heE;   // folded phase 3

        // reduce over jp groups (lane bits 3,4); lanes jp==0 store n-exclusive
        #pragma unroll
        for (int n = 0; n < 4; n++) {
            #pragma unroll
            for (int o = 8; o <= 16; o <<= 1) {
                cmx[n] += __shfl_xor_sync(~0u, cmx[n], o);
                cmy[n] += __shfl_xor_sync(~0u, cmy[n], o);
                cmz[n] += __shfl_xor_sync(~0u, cmz[n], o);
            }
        }
        if (jp == 0) {
            #pragma unroll
            for (int n = 0; n < 4; n++) {
                sm[O_CMX + nb + n] = cmx[n];
                sm[O_CMY + nb + n] = cmy[n];
                sm[O_CMZ + nb + n] = cmz[n];
            }
        }
    }
    __syncthreads();

    // ---- phase 5: comb_sum / comb_norm / delta_v ----
    float* cn    = sm + O_CN;
    float* p1_s  = sm + O_P1;
    float* hcomb = sm + O_HCOMB;
    float* n1_s  = sm + O_N1;
    float* hn_s  = sm + O_HN;
    float* part  = sm + O_CMX;    // reuse (cm dead after reads below)
    float* cat   = sm + O_HET;    // reuse (heT dead): [384]
    const float invN = 1.f/256.f;
    float csx = sm[O_CMX + tid]*invN, csy = sm[O_CMY + tid]*invN, csz = sm[O_CMZ + tid]*invN;
    cn[tid] = csx*csx + csy*csy + csz*csz;
    float wv = Wv_mix[tid];
    float4 dv4 = block_red4<0>(make_float4(wv*csx, wv*csy, wv*csz, 0.f), tid, red);
    // build cat (hi, he_e; hcomb appended after it exists)
    cat[64 + tid] = he_e[tid];
    if (tid < 64) cat[tid] = hi_s[tid];

    // ---- phase 6: tail MLPs, 4-way split over 256 threads ----
    const int g6 = tid >> 6, o6 = tid & 63;
    {   // p1: 256 -> 64
        float a = 0.f;
        const float* wp = Wp1 + g6*64*64 + o6;
        const float* cnp = cn + g6*64;
        #pragma unroll 4
        for (int c = 0; c < 64; c++) a += cnp[c] * wp[c*64];
        part[tid] = a;
    }
    __syncthreads();
    if (tid < 64) {
        float a = bp1[tid] + part[tid] + part[64+tid] + part[128+tid] + part[192+tid];
        p1_s[tid] = siluf(a);
    }
    __syncthreads();
    {   // p2: 64 -> 64
        float a = 0.f;
        const float* wp = Wp2 + g6*16*64 + o6;
        #pragma unroll
        for (int f = 0; f < 16; f++) a += p1_s[g6*16+f] * wp[f*64];
        part[tid] = a;
    }
    __syncthreads();
    if (tid < 64) {
        float a = bp2[tid] + part[tid] + part[64+tid] + part[128+tid] + part[192+tid];
        float hc = siluf(a);
        hcomb[tid] = hc;
        cat[320 + tid] = hc;
    }
    __syncthreads();
    {   // n1: 384 -> 64
        float a = 0.f;
        const float* wp = Wn1 + g6*96*64 + o6;
        const float* cp = cat + g6*96;
        #pragma unroll 4
        for (int r = 0; r < 96; r++) a += cp[r] * wp[r*64];
        part[tid] = a;
    }
    __syncthreads();
    if (tid < 64) {
        float a = bn1[tid] + part[tid] + part[64+tid] + part[128+tid] + part[192+tid];
        n1_s[tid] = siluf(a);
    }
    __syncthreads();
    {   // n2: 64 -> 64
        float a = 0.f;
        const float* wp = Wn2 + g6*16*64 + o6;
        #pragma unroll
        for (int f = 0; f < 16; f++) a += n1_s[g6*16+f] * wp[f*64];
        part[tid] = a;
    }
    __syncthreads();
    if (tid < 64) {
        float a = bn2[tid] + part[tid] + part[64+tid] + part[128+tid] + part[192+tid];
        float hv = hi_s[tid] + siluf(a);
        hn_s[tid] = hv;
        outH[nodeI*64+tid] = hv;
    }
    __syncthreads();
    {   // vel1: 64 -> 64
        float a = 0.f;
        const float* wp = Wvel1 + g6*16*64 + o6;
        #pragma unroll
        for (int f = 0; f < 16; f++) a += hn_s[g6*16+f] * wp[f*64];
        part[tid] = a;
    }
    __syncthreads();
    float vl = 0.f;
    if (tid < 64) {
        float a = bvel1[tid] + part[tid] + part[64+tid] + part[128+tid] + part[192+tid];
        vl = siluf(a) * Wvel2[tid];
    }
    float4 vs = block_red4<0>(make_float4(vl, 0.f, 0.f, 0.f), tid, red);
    if (tid == 0) {
        float scale = 2.f * sigm(vs.x);
        float dvv[3] = {dv4.x, dv4.y, dv4.z};
        #pragma unroll
        for (int t = 0; t < 3; t++) {
            float vn = dvv[t] + scale * v[nodeI*3+t];
            outV[nodeI*3+t] = vn;
            outX[nodeI*3+t] = x[nodeI*3+t] + vn;
        }
    }
}

// ---------------- launch ----------------
extern "C" void kernel_launch(void* const* d_in, const int* in_sizes, int n_in,
                              void* d_out, int out_size) {
    const float* h      = (const float*)d_in[0];
    const float* x      = (const float*)d_in[1];
    const float* v      = (const float*)d_in[2];
    const float* means  = (const float*)d_in[3];
    const float* betas  = (const float*)d_in[4];
    const float* W_in   = (const float*)d_in[5];
    const float* b_in   = (const float*)d_in[6];
    const float* W_o1   = (const float*)d_in[7];
    const float* b_o1   = (const float*)d_in[8];
    const float* W_o2   = (const float*)d_in[9];
    const float* b_o2   = (const float*)d_in[10];
    const float* Ws     = (const float*)d_in[11];
    const float* bs     = (const float*)d_in[12];
    const float* lgam   = (const float*)d_in[13];
    const float* Wx     = (const float*)d_in[14];
    const float* Wp1    = (const float*)d_in[15];
    const float* bp1    = (const float*)d_in[16];
    const float* Wp2    = (const float*)d_in[17];
    const float* bp2    = (const float*)d_in[18];
    const float* Wn1    = (const float*)d_in[19];
    const float* bn1    = (const float*)d_in[20];
    const float* Wn2    = (const float*)d_in[21];
    const float* bn2    = (const float*)d_in[22];
    const float* Wv_mix = (const float*)d_in[23];
    const float* Wvel1  = (const float*)d_in[24];
    const float* bvel1  = (const float*)d_in[25];
    const float* Wvel2  = (const float*)d_in[26];

    float* out  = (float*)d_out;
    float* outH = out;
    float* outX = out + BB*NN*FF;
    float* outV = outX + BB*NN*3;

    cudaFuncSetAttribute(sake_kernel, cudaFuncAttributeMaxDynamicSharedMemorySize, SMEM_BYTES);

    prenode_kernel<<<BB*NN, 128>>>(h, W_in, W_o1);
    sake_kernel<<<BB*NN, 256, SMEM_BYTES>>>(
        h, x, v, means, betas, b_in, W_o1, b_o1, W_o2, b_o2,
        Ws, bs, lgam, Wx, Wp1, bp1, Wp2, bp2,
        Wn1, bn1, Wn2, bn2, Wv_mix, Wvel1, bvel1, Wvel2,
        outH, outX, outV);
}